// round 8
// baseline (speedup 1.0000x reference)
#include <cuda_runtime.h>
#include <cuda_bf16.h>
#include <cstdint>

// BoxCrop: crop -> aspect-preserving bilinear resize (long side = 336) -> pad(127)
// images: [64, 3, 768, 768] f32, boxes: [64, 4] i32 (XYWH), out: [64, 3, 336, 336] f32
// Two-phase: (1) precompute per-image x/y resample tables (indices+weights+valid),
// (2) hot kernel = pure gather+blend, 2 px/thread, float2 stores, immediate
// channel offsets on the gathers.

#define O_SIZE   336
#define IMG_H    768
#define IMG_W    768
#define IMG_HW   (IMG_H * IMG_W)
#define FILL_V   127.0f
#define GROUPS_X 168         // 336 / 2
#define BATCH    64

// x-table entry: {x0, x1, wx(bits), valid} ; y-table entry: {r0, r1, wy(bits), valid}
__device__ int4 g_xtab[BATCH * O_SIZE];
__device__ int4 g_ytab[BATCH * O_SIZE];

__global__ void __launch_bounds__(O_SIZE) precompute_kernel(const int* __restrict__ boxes)
{
    const int b = blockIdx.x;
    const int i = threadIdx.x;          // output coordinate 0..335

    const int4 box = __ldg((const int4*)boxes + b);
    const int xb = box.x, yb = box.y, wb = box.z, hb = box.w;
    const float wf = (float)wb;
    const float hf = (float)hb;

    // Match JAX fp32 math: scale = 336/max; new_* = round-half-even(wf*scale)
    const float scale = 336.0f / fmaxf(wf, hf);
    const int new_w = (int)rintf(wf * scale);
    const int new_h = (int)rintf(hf * scale);
    const int pad_top  = (hb <  wb) ? (O_SIZE - new_h) / 2 : 0;
    const int pad_left = (hb >= wb) ? (O_SIZE - new_w) / 2 : 0;

    // ---- x entry ----
    {
        const int ix = i - pad_left;
        const int valid = ((unsigned)ix < (unsigned)new_w) ? 1 : 0;
        const float src_x = (float)xb + (((float)ix + 0.5f) * wf) / (float)new_w - 0.5f;
        const float x0f = floorf(src_x);
        const float wx  = src_x - x0f;
        const int xlo = xb, xhi = xb + wb - 1;
        const int x0i = (int)x0f;
        const int x0 = min(max(x0i,     xlo), xhi);   // clamp from UNCLAMPED index
        const int x1 = min(max(x0i + 1, xlo), xhi);
        g_xtab[b * O_SIZE + i] = make_int4(x0, x1, __float_as_int(wx), valid);
    }

    // ---- y entry ----
    {
        const int iy = i - pad_top;
        const int valid = ((unsigned)iy < (unsigned)new_h) ? 1 : 0;
        const float src_y = (float)yb + (((float)iy + 0.5f) * hf) / (float)new_h - 0.5f;
        const float y0f = floorf(src_y);
        const float wy  = src_y - y0f;
        const int ylo = yb, yhi = yb + hb - 1;
        const int y0i = (int)y0f;
        const int y0 = min(max(y0i,     ylo), yhi);
        const int y1 = min(max(y0i + 1, ylo), yhi);
        g_ytab[b * O_SIZE + i] = make_int4(y0 * IMG_W, y1 * IMG_W, __float_as_int(wy), valid);
    }
}

__global__ void __launch_bounds__(256) boxcrop_kernel(
    const float* __restrict__ images,
    float* __restrict__ out)
{
    const int b  = blockIdx.z;
    const int g  = blockIdx.x * blockDim.x + threadIdx.x;   // x-group index
    const int oy = blockIdx.y * blockDim.y + threadIdx.y;
    if (g >= GROUPS_X || oy >= O_SIZE) return;
    const int ox0 = g * 2;

    float2* outp = (float2*)(out + ((size_t)b * 3) * (O_SIZE * O_SIZE) + oy * O_SIZE + ox0);
    const int cstride2 = (O_SIZE * O_SIZE) / 2;
    const float2 fill2 = make_float2(FILL_V, FILL_V);

    const int4 yt = __ldg(&g_ytab[b * O_SIZE + oy]);      // broadcast across warp
    if (yt.w == 0) {
        outp[0]            = fill2;
        outp[cstride2]     = fill2;
        outp[2 * cstride2] = fill2;
        return;
    }

    const int4 xt0 = __ldg(&g_xtab[b * O_SIZE + ox0]);     // coalesced
    const int4 xt1 = __ldg(&g_xtab[b * O_SIZE + ox0 + 1]);

    if ((xt0.w | xt1.w) == 0) {
        outp[0]            = fill2;
        outp[cstride2]     = fill2;
        outp[2 * cstride2] = fill2;
        return;
    }

    const int r0 = yt.x;
    const int r1 = yt.y;
    const float wy  = __int_as_float(yt.z);
    const float owy = 1.0f - wy;

    const float* img = images + (size_t)b * 3 * IMG_HW;

    // 4 base pointers; channel strides are compile-time immediates in the LDG.
    const float* p00a = img + r0 + xt0.x;
    const float* p01a = img + r0 + xt0.y;
    const float* p10a = img + r1 + xt0.x;
    const float* p11a = img + r1 + xt0.y;
    const float* p00b = img + r0 + xt1.x;
    const float* p01b = img + r0 + xt1.y;
    const float* p10b = img + r1 + xt1.x;
    const float* p11b = img + r1 + xt1.y;

    float v00a[3], v01a[3], v10a[3], v11a[3];
    float v00b[3], v01b[3], v10b[3], v11b[3];
    #pragma unroll
    for (int c = 0; c < 3; c++) {
        v00a[c] = __ldg(p00a + c * IMG_HW);
        v01a[c] = __ldg(p01a + c * IMG_HW);
        v10a[c] = __ldg(p10a + c * IMG_HW);
        v11a[c] = __ldg(p11a + c * IMG_HW);
        v00b[c] = __ldg(p00b + c * IMG_HW);
        v01b[c] = __ldg(p01b + c * IMG_HW);
        v10b[c] = __ldg(p10b + c * IMG_HW);
        v11b[c] = __ldg(p11b + c * IMG_HW);
    }

    const float wxa = __int_as_float(xt0.z), owxa = 1.0f - wxa;
    const float wxb = __int_as_float(xt1.z), owxb = 1.0f - wxb;

    #pragma unroll
    for (int c = 0; c < 3; c++) {
        const float topa = v00a[c] * owxa + v01a[c] * wxa;
        const float bota = v10a[c] * owxa + v11a[c] * wxa;
        const float vala = topa * owy + bota * wy;
        const float topb = v00b[c] * owxb + v01b[c] * wxb;
        const float botb = v10b[c] * owxb + v11b[c] * wxb;
        const float valb = topb * owy + botb * wy;
        float2 r;
        r.x = xt0.w ? vala : FILL_V;
        r.y = xt1.w ? valb : FILL_V;
        outp[c * cstride2] = r;
    }
}

extern "C" void kernel_launch(void* const* d_in, const int* in_sizes, int n_in,
                              void* d_out, int out_size)
{
    const float* images = (const float*)d_in[0];
    const int*   boxes  = (const int*)d_in[1];
    float*       out    = (float*)d_out;

    precompute_kernel<<<BATCH, O_SIZE>>>(boxes);

    dim3 block(32, 8, 1);
    dim3 grid((GROUPS_X + 31) / 32, (O_SIZE + 7) / 8, BATCH);
    boxcrop_kernel<<<grid, block>>>(images, out);
}

// round 9
// speedup vs baseline: 1.1136x; 1.1136x over previous
#include <cuda_runtime.h>
#include <cuda_bf16.h>
#include <cstdint>

// BoxCrop: crop -> aspect-preserving bilinear resize (long side = 336) -> pad(127)
// images: [64, 3, 768, 768] f32, boxes: [64, 4] i32 (XYWH), out: [64, 3, 336, 336] f32
// Single kernel: per-block smem tables (72 threads compute x/y indices+weights once),
// then pure gather+blend hot path, 2 px/thread, batched loads, float2 stores.

#define O_SIZE   336
#define IMG_H    768
#define IMG_W    768
#define IMG_HW   (IMG_H * IMG_W)
#define FILL_V   127.0f
#define TPB_X    32
#define TPB_Y    8
#define XBLK     64          // pixels in x per block (32 threads * 2 px)

__global__ void __launch_bounds__(256) boxcrop_kernel(
    const float* __restrict__ images,
    const int* __restrict__ boxes,
    float* __restrict__ out)
{
    __shared__ int4 sx[XBLK];   // {x0, x1, wx bits, valid}
    __shared__ int4 sy[TPB_Y];  // {r0, r1, wy bits, valid}

    const int b   = blockIdx.z;
    const int tid = threadIdx.y * TPB_X + threadIdx.x;

    // ---- table build: 72 threads compute entries once per block ----
    if (tid < XBLK + TPB_Y) {
        const int4 box = __ldg((const int4*)boxes + b);
        const int xb = box.x, yb = box.y, wb = box.z, hb = box.w;
        const float wf = (float)wb;
        const float hf = (float)hb;

        // Match JAX fp32 math: scale = 336/max; round-half-even via rintf
        const float scale = 336.0f / fmaxf(wf, hf);
        const int new_w = (int)rintf(wf * scale);
        const int new_h = (int)rintf(hf * scale);
        const int pad_top  = (hb <  wb) ? (O_SIZE - new_h) / 2 : 0;
        const int pad_left = (hb >= wb) ? (O_SIZE - new_w) / 2 : 0;

        if (tid < XBLK) {
            const int i = blockIdx.x * XBLK + tid;        // ox
            if (i < O_SIZE) {
                const int ix = i - pad_left;
                const int valid = ((unsigned)ix < (unsigned)new_w) ? 1 : 0;
                const float src_x = (float)xb + (((float)ix + 0.5f) * wf) / (float)new_w - 0.5f;
                const float x0f = floorf(src_x);
                const float wx  = src_x - x0f;
                const int xlo = xb, xhi = xb + wb - 1;
                const int x0i = (int)x0f;
                const int x0 = min(max(x0i,     xlo), xhi);   // clamp from UNCLAMPED idx
                const int x1 = min(max(x0i + 1, xlo), xhi);
                sx[tid] = make_int4(x0, x1, __float_as_int(wx), valid);
            }
        } else {
            const int i = blockIdx.y * TPB_Y + (tid - XBLK);  // oy (always < 336)
            const int iy = i - pad_top;
            const int valid = ((unsigned)iy < (unsigned)new_h) ? 1 : 0;
            const float src_y = (float)yb + (((float)iy + 0.5f) * hf) / (float)new_h - 0.5f;
            const float y0f = floorf(src_y);
            const float wy  = src_y - y0f;
            const int ylo = yb, yhi = yb + hb - 1;
            const int y0i = (int)y0f;
            const int y0 = min(max(y0i,     ylo), yhi);
            const int y1 = min(max(y0i + 1, ylo), yhi);
            sy[tid - XBLK] = make_int4(y0 * IMG_W, y1 * IMG_W, __float_as_int(wy), valid);
        }
    }
    __syncthreads();

    // ---- hot path ----
    const int ox0 = blockIdx.x * XBLK + threadIdx.x * 2;
    const int oy  = blockIdx.y * TPB_Y + threadIdx.y;
    if (ox0 >= O_SIZE) return;

    float2* outp = (float2*)(out + ((size_t)b * 3) * (O_SIZE * O_SIZE) + oy * O_SIZE + ox0);
    const int cstride2 = (O_SIZE * O_SIZE) / 2;
    const float2 fill2 = make_float2(FILL_V, FILL_V);

    const int4 yt  = sy[threadIdx.y];
    const int4 xt0 = sx[threadIdx.x * 2];
    const int4 xt1 = sx[threadIdx.x * 2 + 1];

    if (yt.w == 0 || (xt0.w | xt1.w) == 0) {
        outp[0]            = fill2;
        outp[cstride2]     = fill2;
        outp[2 * cstride2] = fill2;
        return;
    }

    const int r0 = yt.x;
    const int r1 = yt.y;
    const float wy  = __int_as_float(yt.z);
    const float owy = 1.0f - wy;

    const float* img = images + (size_t)b * 3 * IMG_HW;

    const float* p00a = img + r0 + xt0.x;
    const float* p01a = img + r0 + xt0.y;
    const float* p10a = img + r1 + xt0.x;
    const float* p11a = img + r1 + xt0.y;
    const float* p00b = img + r0 + xt1.x;
    const float* p01b = img + r0 + xt1.y;
    const float* p10b = img + r1 + xt1.x;
    const float* p11b = img + r1 + xt1.y;

    // batch all 24 gathers (channel strides are compile-time immediates)
    float v00a[3], v01a[3], v10a[3], v11a[3];
    float v00b[3], v01b[3], v10b[3], v11b[3];
    #pragma unroll
    for (int c = 0; c < 3; c++) {
        v00a[c] = __ldg(p00a + c * IMG_HW);
        v01a[c] = __ldg(p01a + c * IMG_HW);
        v10a[c] = __ldg(p10a + c * IMG_HW);
        v11a[c] = __ldg(p11a + c * IMG_HW);
        v00b[c] = __ldg(p00b + c * IMG_HW);
        v01b[c] = __ldg(p01b + c * IMG_HW);
        v10b[c] = __ldg(p10b + c * IMG_HW);
        v11b[c] = __ldg(p11b + c * IMG_HW);
    }

    const float wxa = __int_as_float(xt0.z), owxa = 1.0f - wxa;
    const float wxb = __int_as_float(xt1.z), owxb = 1.0f - wxb;

    #pragma unroll
    for (int c = 0; c < 3; c++) {
        const float topa = v00a[c] * owxa + v01a[c] * wxa;
        const float bota = v10a[c] * owxa + v11a[c] * wxa;
        const float vala = topa * owy + bota * wy;
        const float topb = v00b[c] * owxb + v01b[c] * wxb;
        const float botb = v10b[c] * owxb + v11b[c] * wxb;
        const float valb = topb * owy + botb * wy;
        float2 r;
        r.x = xt0.w ? vala : FILL_V;
        r.y = xt1.w ? valb : FILL_V;
        outp[c * cstride2] = r;
    }
}

extern "C" void kernel_launch(void* const* d_in, const int* in_sizes, int n_in,
                              void* d_out, int out_size)
{
    const float* images = (const float*)d_in[0];
    const int*   boxes  = (const int*)d_in[1];
    float*       out    = (float*)d_out;

    dim3 block(TPB_X, TPB_Y, 1);
    dim3 grid((O_SIZE + XBLK - 1) / XBLK, O_SIZE / TPB_Y, 64);   // 6 x 42 x 64
    boxcrop_kernel<<<grid, block>>>(images, boxes, out);
}

// round 10
// speedup vs baseline: 1.3062x; 1.1729x over previous
#include <cuda_runtime.h>
#include <cuda_bf16.h>
#include <cstdint>

// BoxCrop: crop -> aspect-preserving bilinear resize (long side = 336) -> pad(127)
// images: [64, 3, 768, 768] f32, boxes: [64, 4] i32 (XYWH), out: [64, 3, 336, 336] f32
// R7 structure (2 px/thread, batched 24 gathers, float2 stores) + fast divides.
// NOTE: exact div kept for new_w/new_h (rintf half-even boundaries are discrete);
// __fdividef on src coords is safe: bilinear interp is continuous across texel
// boundaries, so ulp-level coordinate error -> ulp-level value error.

#define O_SIZE   336
#define IMG_H    768
#define IMG_W    768
#define IMG_HW   (IMG_H * IMG_W)
#define FILL_V   127.0f
#define GROUPS_X 168         // 336 / 2

__global__ void __launch_bounds__(256) boxcrop_kernel(
    const float* __restrict__ images,
    const int* __restrict__ boxes,
    float* __restrict__ out)
{
    const int b  = blockIdx.z;
    const int g  = blockIdx.x * blockDim.x + threadIdx.x;   // x-group index
    const int oy = blockIdx.y * blockDim.y + threadIdx.y;
    if (g >= GROUPS_X || oy >= O_SIZE) return;
    const int ox0 = g * 2;

    const int4 box = __ldg((const int4*)boxes + b);
    const int xb = box.x, yb = box.y, wb = box.z, hb = box.w;
    const float wf = (float)wb;
    const float hf = (float)hb;

    // Exact fp32 here: feeds rintf (round-half-even), discrete result.
    const float scale = 336.0f / fmaxf(wf, hf);
    const int new_w = (int)rintf(wf * scale);
    const int new_h = (int)rintf(hf * scale);
    const int pad_top  = (hb <  wb) ? (O_SIZE - new_h) / 2 : 0;
    const int pad_left = (hb >= wb) ? (O_SIZE - new_w) / 2 : 0;

    float2* outp = (float2*)(out + ((size_t)b * 3) * (O_SIZE * O_SIZE) + oy * O_SIZE + ox0);
    const int cstride2 = (O_SIZE * O_SIZE) / 2;

    const int iy  = oy  - pad_top;
    const int ix0 = ox0 - pad_left;

    const float2 fill2 = make_float2(FILL_V, FILL_V);

    if ((unsigned)iy >= (unsigned)new_h || ix0 + 1 < 0 || ix0 >= new_w) {
        outp[0]            = fill2;
        outp[cstride2]     = fill2;
        outp[2 * cstride2] = fill2;
        return;
    }

    // ---- y side (once per thread, fast divide) ----
    const float src_y = ((float)yb - 0.5f) + __fdividef(((float)iy + 0.5f) * hf, (float)new_h);
    const float y0f = floorf(src_y);
    const float wy  = src_y - y0f;
    const int ylo = yb, yhi = yb + hb - 1;
    const int y0i = (int)y0f;
    const int y0 = min(max(y0i,     ylo), yhi);
    const int y1 = min(max(y0i + 1, ylo), yhi);
    const int r0 = y0 * IMG_W;
    const int r1 = y1 * IMG_W;
    const float owy = 1.0f - wy;

    // ---- x side (per pixel, clamp from UNCLAMPED floor index — JAX semantics) ----
    int   xi0[2], xi1[2];
    float wxv[2];
    const int xlo = xb, xhi = xb + wb - 1;
    const float new_wf = (float)new_w;
    const float xbm = (float)xb - 0.5f;
    #pragma unroll
    for (int j = 0; j < 2; j++) {
        const int ix = ix0 + j;
        const float src_x = xbm + __fdividef(((float)ix + 0.5f) * wf, new_wf);
        const float x0f = floorf(src_x);
        wxv[j] = src_x - x0f;
        const int x0i = (int)x0f;
        xi0[j] = min(max(x0i,     xlo), xhi);
        xi1[j] = min(max(x0i + 1, xlo), xhi);
    }

    const float* img = images + (size_t)b * 3 * IMG_HW;

    // ---- batch all 24 gather loads (3 channels x 2 px x 4 taps) for MLP ----
    float v00[3][2], v01[3][2], v10[3][2], v11[3][2];
    #pragma unroll
    for (int c = 0; c < 3; c++) {
        const float* p = img + c * IMG_HW;
        #pragma unroll
        for (int j = 0; j < 2; j++) {
            v00[c][j] = __ldg(p + r0 + xi0[j]);
            v01[c][j] = __ldg(p + r0 + xi1[j]);
            v10[c][j] = __ldg(p + r1 + xi0[j]);
            v11[c][j] = __ldg(p + r1 + xi1[j]);
        }
    }

    // ---- blend + store ----
    #pragma unroll
    for (int c = 0; c < 3; c++) {
        float r[2];
        #pragma unroll
        for (int j = 0; j < 2; j++) {
            const float wx  = wxv[j];
            const float owx = 1.0f - wx;
            const float top = v00[c][j] * owx + v01[c][j] * wx;
            const float bot = v10[c][j] * owx + v11[c][j] * wx;
            const float val = top * owy + bot * wy;
            r[j] = ((unsigned)(ix0 + j) < (unsigned)new_w) ? val : FILL_V;
        }
        outp[c * cstride2] = make_float2(r[0], r[1]);
    }
}

extern "C" void kernel_launch(void* const* d_in, const int* in_sizes, int n_in,
                              void* d_out, int out_size)
{
    const float* images = (const float*)d_in[0];
    const int*   boxes  = (const int*)d_in[1];
    float*       out    = (float*)d_out;

    dim3 block(32, 8, 1);
    dim3 grid((GROUPS_X + 31) / 32, (O_SIZE + 7) / 8, 64);
    boxcrop_kernel<<<grid, block>>>(images, boxes, out);
}

// round 11
// speedup vs baseline: 1.3169x; 1.0082x over previous
#include <cuda_runtime.h>
#include <cuda_bf16.h>
#include <cstdint>

// BoxCrop: crop -> aspect-preserving bilinear resize (long side = 336) -> pad(127)
// images: [64, 3, 768, 768] f32, boxes: [64, 4] i32 (XYWH), out: [64, 3, 336, 336] f32
// R10 structure (2 px/thread, batched 24 gathers, float2 stores, fast divides)
// + factored 4-tap weights (1 MUL + 3 FMA per channel) + incremental src_x.

#define O_SIZE   336
#define IMG_H    768
#define IMG_W    768
#define IMG_HW   (IMG_H * IMG_W)
#define FILL_V   127.0f
#define GROUPS_X 168         // 336 / 2

__global__ void __launch_bounds__(256) boxcrop_kernel(
    const float* __restrict__ images,
    const int* __restrict__ boxes,
    float* __restrict__ out)
{
    const int b  = blockIdx.z;
    const int g  = blockIdx.x * blockDim.x + threadIdx.x;   // x-group index
    const int oy = blockIdx.y * blockDim.y + threadIdx.y;
    if (g >= GROUPS_X || oy >= O_SIZE) return;
    const int ox0 = g * 2;

    const int4 box = __ldg((const int4*)boxes + b);
    const int xb = box.x, yb = box.y, wb = box.z, hb = box.w;
    const float wf = (float)wb;
    const float hf = (float)hb;

    // Exact fp32 here: feeds rintf (round-half-even), discrete result.
    const float scale = 336.0f / fmaxf(wf, hf);
    const int new_w = (int)rintf(wf * scale);
    const int new_h = (int)rintf(hf * scale);
    const int pad_top  = (hb <  wb) ? (O_SIZE - new_h) / 2 : 0;
    const int pad_left = (hb >= wb) ? (O_SIZE - new_w) / 2 : 0;

    float2* outp = (float2*)(out + ((size_t)b * 3) * (O_SIZE * O_SIZE) + oy * O_SIZE + ox0);
    const int cstride2 = (O_SIZE * O_SIZE) / 2;

    const int iy  = oy  - pad_top;
    const int ix0 = ox0 - pad_left;

    const float2 fill2 = make_float2(FILL_V, FILL_V);

    if ((unsigned)iy >= (unsigned)new_h || ix0 + 1 < 0 || ix0 >= new_w) {
        outp[0]            = fill2;
        outp[cstride2]     = fill2;
        outp[2 * cstride2] = fill2;
        return;
    }

    // ---- y side (once per thread, fast divide) ----
    const float src_y = ((float)yb - 0.5f) + __fdividef(((float)iy + 0.5f) * hf, (float)new_h);
    const float y0f = floorf(src_y);
    const float wy  = src_y - y0f;
    const int ylo = yb, yhi = yb + hb - 1;
    const int y0i = (int)y0f;
    const int y0 = min(max(y0i,     ylo), yhi);
    const int y1 = min(max(y0i + 1, ylo), yhi);
    const int r0 = y0 * IMG_W;
    const int r1 = y1 * IMG_W;
    const float owy = 1.0f - wy;

    // ---- x side: one divide + incremental step; clamp from UNCLAMPED floor ----
    int   xi0[2], xi1[2];
    float w00[2], w01[2], w10[2], w11[2];
    const int xlo = xb, xhi = xb + wb - 1;
    const float new_wf = (float)new_w;
    const float xbm = (float)xb - 0.5f;
    const float step = __fdividef(wf, new_wf);               // per-pixel src advance
    float src_x = xbm + __fdividef(((float)ix0 + 0.5f) * wf, new_wf);
    #pragma unroll
    for (int j = 0; j < 2; j++) {
        const float x0f = floorf(src_x);
        const float wx  = src_x - x0f;
        const float owx = 1.0f - wx;
        w00[j] = owx * owy;  w01[j] = wx * owy;
        w10[j] = owx * wy;   w11[j] = wx * wy;
        const int x0i = (int)x0f;
        xi0[j] = min(max(x0i,     xlo), xhi);
        xi1[j] = min(max(x0i + 1, xlo), xhi);
        src_x += step;
    }

    const float* img = images + (size_t)b * 3 * IMG_HW;

    // ---- batch all 24 gather loads (3 channels x 2 px x 4 taps) for MLP ----
    float v00[3][2], v01[3][2], v10[3][2], v11[3][2];
    #pragma unroll
    for (int c = 0; c < 3; c++) {
        const float* p = img + c * IMG_HW;
        #pragma unroll
        for (int j = 0; j < 2; j++) {
            v00[c][j] = __ldg(p + r0 + xi0[j]);
            v01[c][j] = __ldg(p + r0 + xi1[j]);
            v10[c][j] = __ldg(p + r1 + xi0[j]);
            v11[c][j] = __ldg(p + r1 + xi1[j]);
        }
    }

    // validity predicates once
    const bool va = ((unsigned)ix0     < (unsigned)new_w);
    const bool vb = ((unsigned)(ix0+1) < (unsigned)new_w);

    // ---- blend (1 MUL + 3 FMA per channel-pixel) + store ----
    #pragma unroll
    for (int c = 0; c < 3; c++) {
        float r[2];
        #pragma unroll
        for (int j = 0; j < 2; j++) {
            float v = v00[c][j] * w00[j];
            v = fmaf(v01[c][j], w01[j], v);
            v = fmaf(v10[c][j], w10[j], v);
            v = fmaf(v11[c][j], w11[j], v);
            r[j] = v;
        }
        float2 o;
        o.x = va ? r[0] : FILL_V;
        o.y = vb ? r[1] : FILL_V;
        outp[c * cstride2] = o;
    }
}

extern "C" void kernel_launch(void* const* d_in, const int* in_sizes, int n_in,
                              void* d_out, int out_size)
{
    const float* images = (const float*)d_in[0];
    const int*   boxes  = (const int*)d_in[1];
    float*       out    = (float*)d_out;

    dim3 block(32, 8, 1);
    dim3 grid((GROUPS_X + 31) / 32, (O_SIZE + 7) / 8, 64);
    boxcrop_kernel<<<grid, block>>>(images, boxes, out);
}